// round 5
// baseline (speedup 1.0000x reference)
#include <cuda_runtime.h>

#define NS   48000
#define NIN  400
#define NSEG 401      // head(60) + 399 interior(120) + tail(60)
#define NB   16
#define NM   64
#define NROWS (NB*NM)

typedef unsigned long long u64;

// Scratch (allocation-free)
__device__ double g_B[(size_t)NROWS * NSEG];   // per-row fp64 segment prefixes
__device__ float  g_F1[NSEG * 120];            // shared frac-cumsum table

// ---- f32x2 helpers (Blackwell packed fp32) ----
__device__ __forceinline__ u64 fma2(u64 a, u64 b, u64 c) {
    u64 d;
    asm("fma.rn.f32x2 %0, %1, %2, %3;" : "=l"(d) : "l"(a), "l"(b), "l"(c));
    return d;
}
__device__ __forceinline__ u64 mul2(u64 a, u64 b) {
    u64 d;
    asm("mul.rn.f32x2 %0, %1, %2;" : "=l"(d) : "l"(a), "l"(b));
    return d;
}
__device__ __forceinline__ u64 add2(u64 a, u64 b) {
    u64 d;
    asm("add.rn.f32x2 %0, %1, %2;" : "=l"(d) : "l"(a), "l"(b));
    return d;
}
__device__ __forceinline__ u64 pk(float lo, float hi) {
    u64 r; asm("mov.b64 %0, {%1,%2};" : "=l"(r) : "f"(lo), "f"(hi)); return r;
}
__device__ __forceinline__ void upk(u64 v, float& lo, float& hi) {
    asm("mov.b64 {%0,%1}, %2;" : "=f"(lo), "=f"(hi) : "l"(v));
}
__device__ __forceinline__ u64 sp(float x) { return pk(x, x); }

// Exact replica of the reference's fp32 position/frac computation.
__device__ __forceinline__ float ref_frac(int j) {
    const float SCALE = 400.0f / 48000.0f;   // fl32(1/120)
    float pos = __fsub_rn(__fmul_rn(__fadd_rn((float)j, 0.5f), SCALE), 0.5f);
    pos = fminf(fmaxf(pos, 0.0f), 399.0f);
    float fi = floorf(pos);
    return __fsub_rn(pos, fi);               // exact (Sterbenz)
}

// Kernel A: row-independent cumulative-frac table (one block per segment).
__global__ void __launch_bounds__(128) f1_kernel() {
    int s = blockIdx.x;
    int cnt   = (s == 0 || s == 400) ? 60 : 120;
    int start = (s == 0) ? 0 : 60 + (s - 1) * 120;
    int m = threadIdx.x;
    double v = (m < cnt) ? (double)ref_frac(start + m) : 0.0;

    int lane = m & 31, w = m >> 5;
    #pragma unroll
    for (int off = 1; off < 32; off <<= 1) {
        double n = __shfl_up_sync(0xFFFFFFFFu, v, off);
        if (lane >= off) v += n;
    }
    __shared__ double wsum[4];
    if (lane == 31) wsum[w] = v;
    __syncthreads();
    double base = 0.0;
    #pragma unroll
    for (int i = 0; i < 3; i++)
        if (i < w) base += wsum[i];
    if (m < cnt) g_F1[s * 120 + m] = (float)(v + base);
    else if (m < 120) g_F1[s * 120 + m] = 0.0f;
}

// Kernel B: per-row exclusive prefix over segment sums, fp64, shuffle-based.
__global__ void __launch_bounds__(512) scan_kernel(const float* __restrict__ params) {
    int r = blockIdx.x;                 // 0..1023 : b*64 + mode
    int b = r >> 6, mode = r & 63;
    const float* F = params + (size_t)(b * 192 + mode) * 400;  // channel 0 = freqs
    int t = threadIdx.x;

    double v = 0.0;
    if (t == 0) {
        v = 60.0 * (double)F[0];        // head: frac == 0 for all 60 samples
    } else if (t <= 399) {
        int i = t - 1;
        double f0 = F[i], f1 = F[i + 1];
        v = 120.0 * f0 + (f1 - f0) * (double)g_F1[t * 120 + 119];
    }

    int lane = t & 31, w = t >> 5;
    double sv = v;
    #pragma unroll
    for (int off = 1; off < 32; off <<= 1) {
        double n = __shfl_up_sync(0xFFFFFFFFu, sv, off);
        if (lane >= off) sv += n;
    }
    __shared__ double wsum[16];
    if (lane == 31) wsum[w] = sv;
    __syncthreads();
    if (w == 0) {
        double x = (lane < 16) ? wsum[lane] : 0.0;
        #pragma unroll
        for (int off = 1; off < 16; off <<= 1) {
            double n = __shfl_up_sync(0xFFFFFFFFu, x, off);
            if (lane >= off) x += n;
        }
        if (lane < 16) wsum[lane] = x;
    }
    __syncthreads();
    double incl = sv + ((w > 0) ? wsum[w - 1] : 0.0);
    if (t <= 400)
        g_B[(size_t)r * NSEG + t] = incl - v;   // exclusive prefix
}

// Kernel C: synthesis. Block=(segment s, batch b), 64 threads, 2 samples/thread.
// Hybrid sin: 9 of every 16 modes via MUFU (__sinf, 2 MUFU slots each), 7 via
// packed f32x2 polynomial on the fma pipe (CW reduce + deg-11 odd minimax).
// Balances MUFU pipe (32 cyc/mode) against fma pipe (30 cyc/mode) -> ~18 cyc/mode.
__global__ void __launch_bounds__(64) synth_kernel(const float* __restrict__ params,
                                                   float* __restrict__ out) {
    int s = blockIdx.x, b = blockIdx.y;
    __shared__ float4 md0[64];   // {ph,ph, f0,f0}
    __shared__ float4 md1[64];   // {dF,dF, a0,a0}
    __shared__ float2 md2[64];   // {da,da}
    int tid = threadIdx.x;

    {
        int mode = tid;          // 64 threads == 64 modes
        const float* F = params + (size_t)(b * 192 + mode) * 400;
        const float* A = F + 64 * 400;      // channel 1 = amps
        const float* P = F + 128 * 400;     // channel 2 = phase
        int i  = (s == 0) ? 0 : ((s <= 399) ? s - 1 : 399);
        int i1 = min(i + 1, 399);
        float f0 = F[i];
        float dw = F[i1] - f0;
        float a0 = A[i];
        float da = A[i1] - a0;
        double t = g_B[(size_t)(b * 64 + mode) * NSEG + s] + (double)P[0];
        double kk = rint(t * 0.15915494309189535);
        double rr = t - kk * 6.283185307179586;
        float ph = (float)rr;
        md0[mode] = make_float4(ph, ph, f0, f0);
        md1[mode] = make_float4(dw, dw, a0, a0);
        md2[mode] = make_float2(da, da);
    }
    __syncthreads();

    int m = tid;
    if (m >= 60) return;                    // 60 threads x 2 samples = 120
    bool interior = (s != 0 && s != 400);
    int start = (s == 0) ? 0 : 60 + (s - 1) * 120;
    int j0 = start + m;
    int j1 = start + m + 60;

    u64 t1p   = pk((float)(m + 1), (float)(m + 61));
    u64 f1p   = pk(g_F1[s * 120 + m], g_F1[s * 120 + m + 60]);
    u64 fracp = pk(ref_frac(j0), interior ? ref_frac(j1) : 0.0f);

    const ulonglong2* M0 = (const ulonglong2*)md0;
    const ulonglong2* M1 = (const ulonglong2*)md1;
    const u64*        M2 = (const u64*)md2;

    // packed constants for the poly path
    const u64 INV2PI = sp(0.15915494f);
    const u64 MAGIC  = sp(12582912.0f);     // 1.5 * 2^23
    const u64 NMAGIC = sp(-12582912.0f);
    const u64 N2PI_A = sp(-6.2831854820251465f);
    const u64 N2PI_B = sp(1.7484556e-07f);
    const u64 C11 = sp(-2.3889859e-08f);
    const u64 C9  = sp( 2.7525562e-06f);
    const u64 C7  = sp(-0.00019840874f);
    const u64 C5  = sp( 0.0083333310f);
    const u64 C3  = sp(-0.16666667f);
    const u64 ONE = sp(1.0f);

    u64 acc2 = pk(0.0f, 0.0f);
#pragma unroll
    for (int k = 0; k < 64; k++) {
        ulonglong2 q0 = M0[k];              // q0.x=(ph,ph) q0.y=(f0,f0)
        ulonglong2 q1 = M1[k];              // q1.x=(dF,dF) q1.y=(a0,a0)
        u64 dd = M2[k];                     // (da,da)
        u64 ph2 = fma2(t1p, q0.y, q0.x);    // ph + t1*f0
        ph2     = fma2(f1p, q1.x, ph2);     // + F1s*dF
        u64 a2  = fma2(fracp, dd, q1.y);    // a0 + frac*da
        if ((k & 15) < 9) {
            // MUFU path (2 MUFU-pipe slots per sin)
            float plo, phi; upk(ph2, plo, phi);
            u64 s2 = pk(__sinf(plo), __sinf(phi));
            acc2 = fma2(a2, s2, acc2);
        } else {
            // fma-pipe path: CW reduce to [-pi,pi] + deg-11 odd minimax
            u64 kb = fma2(ph2, INV2PI, MAGIC);
            u64 kr = add2(kb, NMAGIC);          // rint(ph/2pi), exact
            u64 r  = fma2(kr, N2PI_A, ph2);
            r      = fma2(kr, N2PI_B, r);
            u64 x2 = mul2(r, r);
            u64 p  = fma2(C11, x2, C9);
            p      = fma2(p,  x2, C7);
            p      = fma2(p,  x2, C5);
            p      = fma2(p,  x2, C3);
            p      = fma2(p,  x2, ONE);
            u64 ar = mul2(a2, r);
            acc2   = fma2(ar, p, acc2);
        }
    }

    float alo, ahi; upk(acc2, alo, ahi);
    out[(size_t)b * NS + j0] = alo;
    if (interior) out[(size_t)b * NS + j1] = ahi;
}

extern "C" void kernel_launch(void* const* d_in, const int* in_sizes, int n_in,
                              void* d_out, int out_size) {
    const float* params = (const float*)d_in[0];
    float* out = (float*)d_out;
    f1_kernel<<<NSEG, 128>>>();
    scan_kernel<<<NROWS, 512>>>(params);
    dim3 grid(NSEG, NB);
    synth_kernel<<<grid, 64>>>(params, out);
}

// round 6
// speedup vs baseline: 1.2061x; 1.2061x over previous
#include <cuda_runtime.h>

#define NS   48000
#define NIN  400
#define NSEG 401      // head(60) + 399 interior(120) + tail(60)
#define NB   16
#define NM   64
#define NROWS (NB*NM)

// Scratch (allocation-free)
__device__ double g_B[(size_t)NROWS * NSEG];   // per-row fp64 segment prefixes
__device__ double g_FT[NSEG];                  // per-segment frac totals (for scan)
__device__ float  g_F1[NSEG * 120];            // shared frac-cumsum table

// Exact replica of the reference's fp32 position/frac computation.
__device__ __forceinline__ float ref_frac(int j) {
    const float SCALE = 400.0f / 48000.0f;   // fl32(1/120)
    float pos = __fsub_rn(__fmul_rn(__fadd_rn((float)j, 0.5f), SCALE), 0.5f);
    pos = fminf(fmaxf(pos, 0.0f), 399.0f);
    float fi = floorf(pos);
    return __fsub_rn(pos, fi);               // exact (Sterbenz)
}

// Kernel A: row-independent cumulative-frac table (one block per segment).
__global__ void __launch_bounds__(128) f1_kernel() {
    int s = blockIdx.x;
    int cnt   = (s == 0 || s == 400) ? 60 : 120;
    int start = (s == 0) ? 0 : 60 + (s - 1) * 120;
    int m = threadIdx.x;
    double v = (m < cnt) ? (double)ref_frac(start + m) : 0.0;

    int lane = m & 31, w = m >> 5;
    #pragma unroll
    for (int off = 1; off < 32; off <<= 1) {
        double n = __shfl_up_sync(0xFFFFFFFFu, v, off);
        if (lane >= off) v += n;
    }
    __shared__ double wsum[4];
    if (lane == 31) wsum[w] = v;
    __syncthreads();
    double base = 0.0;
    #pragma unroll
    for (int i = 0; i < 3; i++)
        if (i < w) base += wsum[i];
    double incl = v + base;
    if (m < cnt) g_F1[s * 120 + m] = (float)incl;
    else if (m < 120) g_F1[s * 120 + m] = 0.0f;
    if (m == cnt - 1) g_FT[s] = incl;        // compact totals for scan
}

// Kernel B: per-row exclusive prefix over segment sums, fp64, shuffle-based.
__global__ void __launch_bounds__(512) scan_kernel(const float* __restrict__ params) {
    int r = blockIdx.x;                 // 0..1023 : b*64 + mode
    int b = r >> 6, mode = r & 63;
    const float* F = params + (size_t)(b * 192 + mode) * 400;  // channel 0 = freqs
    int t = threadIdx.x;

    double v = 0.0;
    if (t == 0) {
        v = 60.0 * (double)F[0];        // head: frac == 0 for all 60 samples
    } else if (t <= 399) {
        int i = t - 1;
        double f0 = F[i], f1 = F[i + 1];
        v = 120.0 * f0 + (f1 - f0) * g_FT[t];
    }

    int lane = t & 31, w = t >> 5;
    double sv = v;
    #pragma unroll
    for (int off = 1; off < 32; off <<= 1) {
        double n = __shfl_up_sync(0xFFFFFFFFu, sv, off);
        if (lane >= off) sv += n;
    }
    __shared__ double wsum[16];
    if (lane == 31) wsum[w] = sv;
    __syncthreads();
    if (w == 0) {
        double x = (lane < 16) ? wsum[lane] : 0.0;
        #pragma unroll
        for (int off = 1; off < 16; off <<= 1) {
            double n = __shfl_up_sync(0xFFFFFFFFu, x, off);
            if (lane >= off) x += n;
        }
        if (lane < 16) wsum[lane] = x;
    }
    __syncthreads();
    double incl = sv + ((w > 0) ? wsum[w - 1] : 0.0);
    if (t <= 400)
        g_B[(size_t)r * NSEG + t] = incl - v;   // exclusive prefix
}

// Kernel C: synthesis. Block=(segment s, batch b), 64 threads, 2 samples/thread.
// Empirical pipe model (fit to R3-R5): MUFU sin ~16 cyc/warp/SMSP, FFMA rt 2,
// f32x2 gives no throughput. Hybrid: ~1/5 of modes evaluated by a scalar
// polynomial on the fma pipe (phase kept in TURNS: magic-rint reduction, then
// deg-11 odd minimax in radians); rest via MUFU. Balances both pipes at
// ~25.5 cyc per 2-sample mode-iter vs 32 MUFU-only.
__global__ void __launch_bounds__(64) synth_kernel(const float* __restrict__ params,
                                                   float* __restrict__ out) {
    int s = blockIdx.x, b = blockIdx.y;
    __shared__ float4 md0[64];   // {base_rad, f0_rad, dF_rad, a0}
    __shared__ float4 md1[64];   // {base_trn, f0_trn, dF_trn, da}
    int tid = threadIdx.x;

    {
        int mode = tid;          // 64 threads == 64 modes
        const float* F = params + (size_t)(b * 192 + mode) * 400;
        const float* A = F + 64 * 400;      // channel 1 = amps
        const float* P = F + 128 * 400;     // channel 2 = phase
        int i  = (s == 0) ? 0 : ((s <= 399) ? s - 1 : 399);
        int i1 = min(i + 1, 399);
        float f0 = F[i];
        float dw = F[i1] - f0;
        float a0 = A[i];
        float da = A[i1] - a0;
        double t  = g_B[(size_t)(b * 64 + mode) * NSEG + s] + (double)P[0];
        double tt = t * 0.15915494309189535;      // phase in turns
        double kk = rint(tt);
        double ft = tt - kk;                      // [-0.5, 0.5] turns
        const float INV2PI_F = 0.15915494f;
        md0[mode] = make_float4((float)(ft * 6.283185307179586), f0, dw, a0);
        md1[mode] = make_float4((float)ft, f0 * INV2PI_F, dw * INV2PI_F, da);
    }
    __syncthreads();

    int m = tid;
    if (m >= 60) return;                    // 60 threads x 2 samples = 120
    bool interior = (s != 0 && s != 400);
    int start = (s == 0) ? 0 : 60 + (s - 1) * 120;
    int j0 = start + m;
    int j1 = start + m + 60;

    float t1a = (float)(m + 1),  t1b = (float)(m + 61);
    float F1a = g_F1[s * 120 + m], F1b = g_F1[s * 120 + m + 60];
    float fra = ref_frac(j0);
    float frb = interior ? ref_frac(j1) : 0.0f;

    const float MAGIC  = 12582912.0f;       // 1.5 * 2^23
    const float TWOPI  = 6.2831853f;
    const float C11 = -2.3889859e-08f;
    const float C9  =  2.7525562e-06f;
    const float C7  = -0.00019840874f;
    const float C5  =  0.0083333310f;
    const float C3  = -0.16666667f;

    float acc_a = 0.0f, acc_b = 0.0f;
#pragma unroll
    for (int k = 0; k < 64; k++) {
        if (k % 5 == 0) {
            // fma-pipe path (13 of 64 modes): turns + magic reduce + poly
            float4 q = md1[k];
            float a0k = md0[k].w, dak = q.w;
            // sample a
            float ph = fmaf(t1a, q.y, q.x); ph = fmaf(F1a, q.z, ph);
            float kr = (ph + MAGIC) - MAGIC;        // rint(ph) in turns
            float r  = (ph - kr) * TWOPI;           // [-pi, pi] radians
            float x2 = r * r;
            float p  = fmaf(C11, x2, C9);
            p = fmaf(p, x2, C7); p = fmaf(p, x2, C5);
            p = fmaf(p, x2, C3); p = fmaf(p, x2, 1.0f);
            float aa = fmaf(dak, fra, a0k);
            acc_a = fmaf(aa * r, p, acc_a);
            // sample b
            float phb = fmaf(t1b, q.y, q.x); phb = fmaf(F1b, q.z, phb);
            float krb = (phb + MAGIC) - MAGIC;
            float rb  = (phb - krb) * TWOPI;
            float xb2 = rb * rb;
            float pb  = fmaf(C11, xb2, C9);
            pb = fmaf(pb, xb2, C7); pb = fmaf(pb, xb2, C5);
            pb = fmaf(pb, xb2, C3); pb = fmaf(pb, xb2, 1.0f);
            float ab = fmaf(dak, frb, a0k);
            acc_b = fmaf(ab * rb, pb, acc_b);
        } else {
            // MUFU path (51 of 64 modes)
            float4 q = md0[k];
            float dak = md1[k].w;
            float ph  = fmaf(t1a, q.y, q.x); ph  = fmaf(F1a, q.z, ph);
            float phb = fmaf(t1b, q.y, q.x); phb = fmaf(F1b, q.z, phb);
            float aa = fmaf(dak, fra, q.w);
            float ab = fmaf(dak, frb, q.w);
            acc_a = fmaf(aa, __sinf(ph),  acc_a);
            acc_b = fmaf(ab, __sinf(phb), acc_b);
        }
    }

    out[(size_t)b * NS + j0] = acc_a;
    if (interior) out[(size_t)b * NS + j1] = acc_b;
}

extern "C" void kernel_launch(void* const* d_in, const int* in_sizes, int n_in,
                              void* d_out, int out_size) {
    const float* params = (const float*)d_in[0];
    float* out = (float*)d_out;
    f1_kernel<<<NSEG, 128>>>();
    scan_kernel<<<NROWS, 512>>>(params);
    dim3 grid(NSEG, NB);
    synth_kernel<<<grid, 64>>>(params, out);
}